// round 9
// baseline (speedup 1.0000x reference)
#include <cuda_runtime.h>

// Problem constants
#define NN 50000      // nodes
#define FF 64         // features
#define HH 2          // heads
#define EE 800000     // edges
#define CC 256        // 2*H*F projected columns per node
#define SLOTS 128     // per-row edge bin capacity (expected max degree ~35)

#define GEMM_BLOCKS 592   // persistent: 2 col-halves x 296 tile streams

// Device scratch (static globals — no runtime allocation)
__device__ float g_qk[(size_t)NN * CC];          // [N,256]: h0:q(64)|k(64), h1:q(64)|k(64)
__device__ int   g_cnt[NN];                      // per-row edge counts / cursors
__device__ int2  g_slots[(size_t)NN * SLOTS];    // per-row bins: (col, edge_id)

// ---------------------------------------------------------------------------
// Kernel 1: qk = x @ W + b   ([N,64] @ [64,256] -> [N,256])
// 2-D register-blocked f32x2 GEMM with crossbar-dedup lane mapping.
// Warp = 8 col-groups (cg=lane&7) x 4 node-groups (ng=lane>>3):
//   W frag: 8 distinct addrs/warp (4-way dedup) = 256B -> 2 crossbar cyc
//   x frag: 4 distinct addrs/warp (8-way dedup) = 32B
//   16 FFMA2 : 6 LDS per p  ->  fma-bound (R8 was crossbar-bound: lane-
//   distinct W frags moved 1024B/warp/p through the 128B/cyc crossbar).
// Block: 8 warps = 4 col-warps x 2 node-warps = 128 cols x 32 nodes.
// Persistent: blockIdx&1 = column half (W half staged once, 32 KB).
// ---------------------------------------------------------------------------
__global__ __launch_bounds__(256) void gemm_kernel(
    const float* __restrict__ x,
    const float* __restrict__ W,
    const float* __restrict__ b)
{
    __shared__ __align__(16) unsigned long long sWt[32 * 128];  // [p][128 cols], 32 KB
    __shared__ __align__(16) unsigned long long xs[32 * 32];    // [node][p], 8 KB

    const int t    = threadIdx.x;
    const int w    = t >> 5;
    const int lane = t & 31;
    const int ch   = blockIdx.x & 1;             // column half
    const int j0   = ch * 128;
    const int cg   = lane & 7;                   // col group
    const int ng   = lane >> 3;                  // node group
    const int jc   = (w & 3) * 32 + 4 * cg;      // 4 cols within the half
    const int nb   = (w >> 2) * 16 + 4 * ng;     // 4 nodes within the tile

    // stage W half, f-paired: sWt[p*128+j] = (W[2p][j0+j], W[2p+1][j0+j])
    for (int idx = t; idx < 32 * 128; idx += 256) {
        int p = idx >> 7, j = idx & 127;
        float a0 = W[(2 * p) * CC + j0 + j];
        float a1 = W[(2 * p + 1) * CC + j0 + j];
        unsigned long long pk;
        asm("mov.b64 %0, {%1,%2};" : "=l"(pk) : "f"(a0), "f"(a1));
        sWt[idx] = pk;
    }
    const float4 b4 = *reinterpret_cast<const float4*>(b + j0 + jc);
    __syncthreads();

    for (int tile = blockIdx.x >> 1; tile * 32 < NN; tile += GEMM_BLOCKS / 2) {
        const int node0 = tile * 32;

        // stage x tile: 32 nodes x 64 f = 512 float4 (zero-pad past NN)
        {
            const float4* x4 = reinterpret_cast<const float4*>(x + (size_t)node0 * FF);
            const int cnt4 = (min(32, NN - node0)) * (FF / 4);
            float4* xs4 = reinterpret_cast<float4*>(xs);
#pragma unroll
            for (int i = 0; i < 2; i++) {
                int idx = t + i * 256;
                xs4[idx] = (idx < cnt4) ? x4[idx]
                                        : make_float4(0.f, 0.f, 0.f, 0.f);
            }
        }
        __syncthreads();

        unsigned long long acc[4][4];            // [node][col]
#pragma unroll
        for (int i = 0; i < 4; i++)
#pragma unroll
            for (int c = 0; c < 4; c++) acc[i][c] = 0ull;

#pragma unroll 8
        for (int p = 0; p < 32; p++) {
            // W pairs for this thread's 4 cols: 2 LDS.128, 4-way warp dedup
            ulonglong2 wva = *reinterpret_cast<const ulonglong2*>(
                &sWt[p * 128 + jc]);
            ulonglong2 wvb = *reinterpret_cast<const ulonglong2*>(
                &sWt[p * 128 + jc + 2]);
            // x pairs for this thread's 4 nodes: 8-way warp dedup
            unsigned long long xv0 = xs[(nb + 0) * 32 + p];
            unsigned long long xv1 = xs[(nb + 1) * 32 + p];
            unsigned long long xv2 = xs[(nb + 2) * 32 + p];
            unsigned long long xv3 = xs[(nb + 3) * 32 + p];

#define FMA2(A, X, WV) asm("fma.rn.f32x2 %0, %1, %2, %0;" : "+l"(A) : "l"(X), "l"(WV))
            FMA2(acc[0][0], xv0, wva.x); FMA2(acc[0][1], xv0, wva.y);
            FMA2(acc[0][2], xv0, wvb.x); FMA2(acc[0][3], xv0, wvb.y);
            FMA2(acc[1][0], xv1, wva.x); FMA2(acc[1][1], xv1, wva.y);
            FMA2(acc[1][2], xv1, wvb.x); FMA2(acc[1][3], xv1, wvb.y);
            FMA2(acc[2][0], xv2, wva.x); FMA2(acc[2][1], xv2, wva.y);
            FMA2(acc[2][2], xv2, wvb.x); FMA2(acc[2][3], xv2, wvb.y);
            FMA2(acc[3][0], xv3, wva.x); FMA2(acc[3][1], xv3, wva.y);
            FMA2(acc[3][2], xv3, wvb.x); FMA2(acc[3][3], xv3, wvb.y);
#undef FMA2
        }

        // reduce f32x2 halves, add bias, store one float4 per node.
        // Lanes with same ng have consecutive jc -> coalesced 128B groups.
#pragma unroll
        for (int i = 0; i < 4; i++) {
            int node = node0 + nb + i;
            if (node < NN) {
                float lo, hi;
                float4 o;
                asm("mov.b64 {%0,%1}, %2;" : "=f"(lo), "=f"(hi) : "l"(acc[i][0]));
                o.x = lo + hi + b4.x;
                asm("mov.b64 {%0,%1}, %2;" : "=f"(lo), "=f"(hi) : "l"(acc[i][1]));
                o.y = lo + hi + b4.y;
                asm("mov.b64 {%0,%1}, %2;" : "=f"(lo), "=f"(hi) : "l"(acc[i][2]));
                o.z = lo + hi + b4.z;
                asm("mov.b64 {%0,%1}, %2;" : "=f"(lo), "=f"(hi) : "l"(acc[i][3]));
                o.w = lo + hi + b4.w;
                *reinterpret_cast<float4*>(
                    &g_qk[(size_t)node * CC + j0 + jc]) = o;
            }
        }
        __syncthreads();   // protect xs before next tile restages
    }
}

// ---------------------------------------------------------------------------
// Kernel 2: bucket edges by source row (order within a row irrelevant)
// ---------------------------------------------------------------------------
__global__ __launch_bounds__(256) void scatter_kernel(const int* __restrict__ ei)
{
    int e = blockIdx.x * blockDim.x + threadIdx.x;
    if (e >= EE) return;
    int row = ei[e];
    int col = ei[EE + e];
    int pos = atomicAdd(&g_cnt[row], 1);
    if (pos < SLOTS)
        g_slots[(size_t)row * SLOTS + pos] = make_int2(col, e);
}

// ---------------------------------------------------------------------------
// Kernel 3 (R3-passing version, measured 52us): one warp per row, 4 edges
// in flight. sub = lane>>4 (edge of pair), h = (lane>>3)&1 (head),
// c = lane&7 (8-float chunk). 8 lanes per (edge,head); 3-shfl reduction.
// ---------------------------------------------------------------------------
__global__ __launch_bounds__(256) void row_kernel(float* __restrict__ out)
{
    __shared__ float exbuf[8][SLOTS][2];         // 8 KB

    const int w    = threadIdx.x >> 5;
    const int lane = threadIdx.x & 31;
    const int row  = blockIdx.x * 8 + w;
    if (row >= NN) return;

    const int sub = lane >> 4;                   // which edge of the pair
    const int h   = (lane >> 3) & 1;             // head
    const int c   = lane & 7;                    // chunk of 8 floats

    const float4* qp = reinterpret_cast<const float4*>(
        g_qk + (size_t)row * CC + h * 128 + c * 8);
    const float4 qa = qp[0];
    const float4 qb = qp[1];

    int deg = g_cnt[row];
    if (deg > SLOTS) deg = SLOTS;
    const int2* sl = g_slots + (size_t)row * SLOTS;

    float denom = 0.0f;                          // valid on lanes 0, 8, 16, 24

    for (int i0 = 0; i0 < deg; i0 += 4) {
        const int iA = i0 + sub;
        const int iB = i0 + 2 + sub;
        const bool vA = iA < deg;
        const bool vB = iB < deg;
        const int colA = vA ? sl[iA].x : 0;
        const int colB = vB ? sl[iB].x : 0;

        const float4* kA = reinterpret_cast<const float4*>(
            g_qk + (size_t)colA * CC + h * 128 + 64 + c * 8);
        const float4* kB = reinterpret_cast<const float4*>(
            g_qk + (size_t)colB * CC + h * 128 + 64 + c * 8);
        float4 ka0 = kA[0], ka1 = kA[1];
        float4 kb0 = kB[0], kb1 = kB[1];

        float sA = qa.x * ka0.x + qa.y * ka0.y + qa.z * ka0.z + qa.w * ka0.w
                 + qb.x * ka1.x + qb.y * ka1.y + qb.z * ka1.z + qb.w * ka1.w;
        float sB = qa.x * kb0.x + qa.y * kb0.y + qa.z * kb0.z + qa.w * kb0.w
                 + qb.x * kb1.x + qb.y * kb1.y + qb.z * kb1.z + qb.w * kb1.w;

        sA += __shfl_xor_sync(0xffffffffu, sA, 1);
        sB += __shfl_xor_sync(0xffffffffu, sB, 1);
        sA += __shfl_xor_sync(0xffffffffu, sA, 2);
        sB += __shfl_xor_sync(0xffffffffu, sB, 2);
        sA += __shfl_xor_sync(0xffffffffu, sA, 4);
        sB += __shfl_xor_sync(0xffffffffu, sB, 4);

        if (c == 0) {
            if (vA) {
                float ex = __expf(sA);           // |s| <~ 15: no max-shift needed
                exbuf[w][iA][h] = ex;
                denom += ex;
            }
            if (vB) {
                float ex = __expf(sB);
                exbuf[w][iB][h] = ex;
                denom += ex;
            }
        }
    }

    float d0 = __shfl_sync(0xffffffffu, denom, 0)
             + __shfl_sync(0xffffffffu, denom, 16);   // head 0
    float d1 = __shfl_sync(0xffffffffu, denom, 8)
             + __shfl_sync(0xffffffffu, denom, 24);   // head 1
    float c0 = 0.5f / d0;
    float c1 = 0.5f / d1;
    __syncwarp();

    for (int i = lane; i < deg; i += 32) {
        int2 sc = sl[i];
        out[sc.y] = exbuf[w][i][0] * c0 + exbuf[w][i][1] * c1;
    }
}

// ---------------------------------------------------------------------------
extern "C" void kernel_launch(void* const* d_in, const int* in_sizes, int n_in,
                              void* d_out, int out_size)
{
    const float* x   = (const float*)d_in[0];    // [50000, 64]
    const float* W   = (const float*)d_in[1];    // [64, 256]
    const float* b   = (const float*)d_in[2];    // [256]
    const int*   ei  = (const int*)  d_in[3];    // [2, 800000]
    float*       out = (float*)d_out;            // [800000]

    (void)in_sizes; (void)n_in; (void)out_size;

    // zero the row cursors (graph-capturable async memset)
    void* cnt_ptr = nullptr;
    cudaGetSymbolAddress(&cnt_ptr, g_cnt);
    cudaMemsetAsync(cnt_ptr, 0, NN * sizeof(int));

    gemm_kernel<<<GEMM_BLOCKS, 256>>>(x, W, b);
    scatter_kernel<<<(EE + 255) / 256, 256>>>(ei);
    row_kernel<<<(NN + 7) / 8, 256>>>(out);
}

// round 12
// speedup vs baseline: 1.3602x; 1.3602x over previous
#include <cuda_runtime.h>

// Problem constants
#define NN 50000      // nodes
#define FF 64         // features
#define HH 2          // heads
#define EE 800000     // edges
#define CC 256        // 2*H*F projected columns per node
#define SLOTS 128     // per-row edge bin capacity (expected max degree ~35)

// Device scratch (static globals — no runtime allocation)
__device__ float g_qk[(size_t)NN * CC];          // [N,256]: h0:q(64)|k(64), h1:q(64)|k(64)
__device__ int   g_cnt[NN];                      // per-row edge counts / cursors
__device__ int2  g_slots[(size_t)NN * SLOTS];    // per-row bins: (col, edge_id)

// ---------------------------------------------------------------------------
// Kernel 1: qk = x @ W + b   ([N,64] @ [64,256] -> [N,256])
// R3-proven structure: 128 threads/block; thread j computes columns j and
// j+128; W columns in registers as f-adjacent f32x2 pairs (128 regs); x tile
// in smem; hot-loop x loads are warp-broadcast LDS.64 -> 1 LDS : 2 FFMA2.
// Delta vs R3: 2 nodes interleaved -> 4 independent FFMA2 chains (R3's two
// chains left fma at 45.6%). __launch_bounds__(128,3) pins regs so we keep
// 3 blocks/SM. p-loop FULLY unrolled (R6 lesson: constant wp indices).
// ---------------------------------------------------------------------------
#define NODES_PER_BLOCK 64

__global__ __launch_bounds__(128, 3) void gemm_kernel(
    const float* __restrict__ x,
    const float* __restrict__ W,
    const float* __restrict__ b)
{
    __shared__ __align__(16) unsigned long long xs[NODES_PER_BLOCK * (FF / 2)]; // 16 KB

    const int j = threadIdx.x;                   // 0..127
    const int node0 = blockIdx.x * NODES_PER_BLOCK;

    // Pack weight columns j and j+128 into f32x2 register pairs (f-adjacent)
    unsigned long long wp0[FF / 2], wp1[FF / 2];
#pragma unroll
    for (int p = 0; p < FF / 2; p++) {
        float a0 = W[(2 * p) * CC + j];
        float a1 = W[(2 * p + 1) * CC + j];
        float c0 = W[(2 * p) * CC + j + 128];
        float c1 = W[(2 * p + 1) * CC + j + 128];
        asm("mov.b64 %0, {%1,%2};" : "=l"(wp0[p]) : "f"(a0), "f"(a1));
        asm("mov.b64 %0, {%1,%2};" : "=l"(wp1[p]) : "f"(c0), "f"(c1));
    }
    const float bj0 = b[j];
    const float bj1 = b[j + 128];

    // stage x tile (coalesced float4 loads; bytes reinterpreted as u64 pairs)
    const int nmax = min(NODES_PER_BLOCK, NN - node0);   // 64, or 16 on last tile
    const int nf4 = nmax * (FF / 4);
    const float4* x4 = reinterpret_cast<const float4*>(x + (size_t)node0 * FF);
    float4* xs4 = reinterpret_cast<float4*>(xs);
    for (int idx = j; idx < nf4; idx += 128) xs4[idx] = x4[idx];
    __syncthreads();

    // nmax is 64 or 16 -> always a multiple of 2
    for (int n0 = 0; n0 < nmax; n0 += 2) {
        unsigned long long accA0 = 0ull, accA1 = 0ull;   // node n0:   cols j, j+128
        unsigned long long accB0 = 0ull, accB1 = 0ull;   // node n0+1: cols j, j+128
        const unsigned long long* xr0 = &xs[(n0 + 0) * (FF / 2)];
        const unsigned long long* xr1 = &xs[(n0 + 1) * (FF / 2)];

#pragma unroll
        for (int p = 0; p < FF / 2; p++) {       // FULL unroll: wp[p] const index
            unsigned long long xpA = xr0[p];     // broadcast LDS.64
            unsigned long long xpB = xr1[p];
            asm("fma.rn.f32x2 %0, %1, %2, %0;" : "+l"(accA0) : "l"(xpA), "l"(wp0[p]));
            asm("fma.rn.f32x2 %0, %1, %2, %0;" : "+l"(accB0) : "l"(xpB), "l"(wp0[p]));
            asm("fma.rn.f32x2 %0, %1, %2, %0;" : "+l"(accA1) : "l"(xpA), "l"(wp1[p]));
            asm("fma.rn.f32x2 %0, %1, %2, %0;" : "+l"(accB1) : "l"(xpB), "l"(wp1[p]));
        }

        float lo, hi;
        asm("mov.b64 {%0,%1}, %2;" : "=f"(lo), "=f"(hi) : "l"(accA0));
        g_qk[(size_t)(node0 + n0 + 0) * CC + j]       = lo + hi + bj0;
        asm("mov.b64 {%0,%1}, %2;" : "=f"(lo), "=f"(hi) : "l"(accA1));
        g_qk[(size_t)(node0 + n0 + 0) * CC + j + 128] = lo + hi + bj1;
        asm("mov.b64 {%0,%1}, %2;" : "=f"(lo), "=f"(hi) : "l"(accB0));
        g_qk[(size_t)(node0 + n0 + 1) * CC + j]       = lo + hi + bj0;
        asm("mov.b64 {%0,%1}, %2;" : "=f"(lo), "=f"(hi) : "l"(accB1));
        g_qk[(size_t)(node0 + n0 + 1) * CC + j + 128] = lo + hi + bj1;
    }
}

// ---------------------------------------------------------------------------
// Kernel 2: bucket edges by source row (order within a row irrelevant)
// ---------------------------------------------------------------------------
__global__ __launch_bounds__(256) void scatter_kernel(const int* __restrict__ ei)
{
    int e = blockIdx.x * blockDim.x + threadIdx.x;
    if (e >= EE) return;
    int row = ei[e];
    int col = ei[EE + e];
    int pos = atomicAdd(&g_cnt[row], 1);
    if (pos < SLOTS)
        g_slots[(size_t)row * SLOTS + pos] = make_int2(col, e);
}

// ---------------------------------------------------------------------------
// Kernel 3 (R3-passing version, measured 52us — the 8-edge variant traps and
// is BANNED): one warp per row, 4 edges in flight. sub = lane>>4 (edge of
// pair), h = (lane>>3)&1 (head), c = lane&7 (8-float chunk). 8 lanes per
// (edge,head); 3-shfl reduction.
// ---------------------------------------------------------------------------
__global__ __launch_bounds__(256) void row_kernel(float* __restrict__ out)
{
    __shared__ float exbuf[8][SLOTS][2];         // 8 KB

    const int w    = threadIdx.x >> 5;
    const int lane = threadIdx.x & 31;
    const int row  = blockIdx.x * 8 + w;
    if (row >= NN) return;

    const int sub = lane >> 4;                   // which edge of the pair
    const int h   = (lane >> 3) & 1;             // head
    const int c   = lane & 7;                    // chunk of 8 floats

    const float4* qp = reinterpret_cast<const float4*>(
        g_qk + (size_t)row * CC + h * 128 + c * 8);
    const float4 qa = qp[0];
    const float4 qb = qp[1];

    int deg = g_cnt[row];
    if (deg > SLOTS) deg = SLOTS;
    const int2* sl = g_slots + (size_t)row * SLOTS;

    float denom = 0.0f;                          // valid on lanes 0, 8, 16, 24

    for (int i0 = 0; i0 < deg; i0 += 4) {
        const int iA = i0 + sub;
        const int iB = i0 + 2 + sub;
        const bool vA = iA < deg;
        const bool vB = iB < deg;
        const int colA = vA ? sl[iA].x : 0;
        const int colB = vB ? sl[iB].x : 0;

        const float4* kA = reinterpret_cast<const float4*>(
            g_qk + (size_t)colA * CC + h * 128 + 64 + c * 8);
        const float4* kB = reinterpret_cast<const float4*>(
            g_qk + (size_t)colB * CC + h * 128 + 64 + c * 8);
        float4 ka0 = kA[0], ka1 = kA[1];
        float4 kb0 = kB[0], kb1 = kB[1];

        float sA = qa.x * ka0.x + qa.y * ka0.y + qa.z * ka0.z + qa.w * ka0.w
                 + qb.x * ka1.x + qb.y * ka1.y + qb.z * ka1.z + qb.w * ka1.w;
        float sB = qa.x * kb0.x + qa.y * kb0.y + qa.z * kb0.z + qa.w * kb0.w
                 + qb.x * kb1.x + qb.y * kb1.y + qb.z * kb1.z + qb.w * kb1.w;

        sA += __shfl_xor_sync(0xffffffffu, sA, 1);
        sB += __shfl_xor_sync(0xffffffffu, sB, 1);
        sA += __shfl_xor_sync(0xffffffffu, sA, 2);
        sB += __shfl_xor_sync(0xffffffffu, sB, 2);
        sA += __shfl_xor_sync(0xffffffffu, sA, 4);
        sB += __shfl_xor_sync(0xffffffffu, sB, 4);

        if (c == 0) {
            if (vA) {
                float ex = __expf(sA);           // |s| <~ 15: no max-shift needed
                exbuf[w][iA][h] = ex;
                denom += ex;
            }
            if (vB) {
                float ex = __expf(sB);
                exbuf[w][iB][h] = ex;
                denom += ex;
            }
        }
    }

    float d0 = __shfl_sync(0xffffffffu, denom, 0)
             + __shfl_sync(0xffffffffu, denom, 16);   // head 0
    float d1 = __shfl_sync(0xffffffffu, denom, 8)
             + __shfl_sync(0xffffffffu, denom, 24);   // head 1
    float c0 = 0.5f / d0;
    float c1 = 0.5f / d1;
    __syncwarp();

    for (int i = lane; i < deg; i += 32) {
        int2 sc = sl[i];
        out[sc.y] = exbuf[w][i][0] * c0 + exbuf[w][i][1] * c1;
    }
}

// ---------------------------------------------------------------------------
extern "C" void kernel_launch(void* const* d_in, const int* in_sizes, int n_in,
                              void* d_out, int out_size)
{
    const float* x   = (const float*)d_in[0];    // [50000, 64]
    const float* W   = (const float*)d_in[1];    // [64, 256]
    const float* b   = (const float*)d_in[2];    // [256]
    const int*   ei  = (const int*)  d_in[3];    // [2, 800000]
    float*       out = (float*)d_out;            // [800000]

    (void)in_sizes; (void)n_in; (void)out_size;

    // zero the row cursors (graph-capturable async memset)
    void* cnt_ptr = nullptr;
    cudaGetSymbolAddress(&cnt_ptr, g_cnt);
    cudaMemsetAsync(cnt_ptr, 0, NN * sizeof(int));

    gemm_kernel<<<(NN + NODES_PER_BLOCK - 1) / NODES_PER_BLOCK, 128>>>(x, W, b);
    scatter_kernel<<<(EE + 255) / 256, 256>>>(ei);
    row_kernel<<<(NN + 7) / 8, 256>>>(out);
}

// round 13
// speedup vs baseline: 1.3865x; 1.0194x over previous
#include <cuda_runtime.h>

// Problem constants
#define NN 50000      // nodes
#define FF 64         // features
#define HH 2          // heads
#define EE 800000     // edges
#define CC 256        // 2*H*F projected columns per node
#define SLOTS 128     // per-row edge bin capacity (expected max degree ~35)

// Device scratch (static globals — no runtime allocation)
__device__ float g_qk[(size_t)NN * CC];          // [N,256]: h0:q(64)|k(64), h1:q(64)|k(64)
__device__ int   g_cnt[NN];                      // per-row edge counts / cursors
__device__ int2  g_slots[(size_t)NN * SLOTS];    // per-row bins: (col, edge_id)

// ---------------------------------------------------------------------------
// Kernel 1 (R12-passing, 42.6us — UNCHANGED): qk = x @ W + b.
// 128 threads/block; thread j computes columns j and j+128; W columns in
// registers as f-adjacent f32x2 pairs; x tile in smem; broadcast LDS.64
// -> 1 LDS : 2 FFMA2; 2 nodes interleaved -> 4 independent FFMA2 chains.
// ---------------------------------------------------------------------------
#define NODES_PER_BLOCK 64

__global__ __launch_bounds__(128, 3) void gemm_kernel(
    const float* __restrict__ x,
    const float* __restrict__ W,
    const float* __restrict__ b)
{
    __shared__ __align__(16) unsigned long long xs[NODES_PER_BLOCK * (FF / 2)]; // 16 KB

    const int j = threadIdx.x;                   // 0..127
    const int node0 = blockIdx.x * NODES_PER_BLOCK;

    unsigned long long wp0[FF / 2], wp1[FF / 2];
#pragma unroll
    for (int p = 0; p < FF / 2; p++) {
        float a0 = W[(2 * p) * CC + j];
        float a1 = W[(2 * p + 1) * CC + j];
        float c0 = W[(2 * p) * CC + j + 128];
        float c1 = W[(2 * p + 1) * CC + j + 128];
        asm("mov.b64 %0, {%1,%2};" : "=l"(wp0[p]) : "f"(a0), "f"(a1));
        asm("mov.b64 %0, {%1,%2};" : "=l"(wp1[p]) : "f"(c0), "f"(c1));
    }
    const float bj0 = b[j];
    const float bj1 = b[j + 128];

    const int nmax = min(NODES_PER_BLOCK, NN - node0);   // 64, or 16 on last tile
    const int nf4 = nmax * (FF / 4);
    const float4* x4 = reinterpret_cast<const float4*>(x + (size_t)node0 * FF);
    float4* xs4 = reinterpret_cast<float4*>(xs);
    for (int idx = j; idx < nf4; idx += 128) xs4[idx] = x4[idx];
    __syncthreads();

    for (int n0 = 0; n0 < nmax; n0 += 2) {
        unsigned long long accA0 = 0ull, accA1 = 0ull;
        unsigned long long accB0 = 0ull, accB1 = 0ull;
        const unsigned long long* xr0 = &xs[(n0 + 0) * (FF / 2)];
        const unsigned long long* xr1 = &xs[(n0 + 1) * (FF / 2)];

#pragma unroll
        for (int p = 0; p < FF / 2; p++) {       // FULL unroll: wp[p] const index
            unsigned long long xpA = xr0[p];     // broadcast LDS.64
            unsigned long long xpB = xr1[p];
            asm("fma.rn.f32x2 %0, %1, %2, %0;" : "+l"(accA0) : "l"(xpA), "l"(wp0[p]));
            asm("fma.rn.f32x2 %0, %1, %2, %0;" : "+l"(accB0) : "l"(xpB), "l"(wp0[p]));
            asm("fma.rn.f32x2 %0, %1, %2, %0;" : "+l"(accA1) : "l"(xpA), "l"(wp1[p]));
            asm("fma.rn.f32x2 %0, %1, %2, %0;" : "+l"(accB1) : "l"(xpB), "l"(wp1[p]));
        }

        float lo, hi;
        asm("mov.b64 {%0,%1}, %2;" : "=f"(lo), "=f"(hi) : "l"(accA0));
        g_qk[(size_t)(node0 + n0 + 0) * CC + j]       = lo + hi + bj0;
        asm("mov.b64 {%0,%1}, %2;" : "=f"(lo), "=f"(hi) : "l"(accA1));
        g_qk[(size_t)(node0 + n0 + 0) * CC + j + 128] = lo + hi + bj1;
        asm("mov.b64 {%0,%1}, %2;" : "=f"(lo), "=f"(hi) : "l"(accB0));
        g_qk[(size_t)(node0 + n0 + 1) * CC + j]       = lo + hi + bj0;
        asm("mov.b64 {%0,%1}, %2;" : "=f"(lo), "=f"(hi) : "l"(accB1));
        g_qk[(size_t)(node0 + n0 + 1) * CC + j + 128] = lo + hi + bj1;
    }
}

// ---------------------------------------------------------------------------
// Kernel 2: bucket edges by source row (order within a row irrelevant)
// ---------------------------------------------------------------------------
__global__ __launch_bounds__(256) void scatter_kernel(const int* __restrict__ ei)
{
    int e = blockIdx.x * blockDim.x + threadIdx.x;
    if (e >= EE) return;
    int row = ei[e];
    int col = ei[EE + e];
    int pos = atomicAdd(&g_cnt[row], 1);
    if (pos < SLOTS)
        g_slots[(size_t)row * SLOTS + pos] = make_int2(col, e);
}

// ---------------------------------------------------------------------------
// Kernel 3: 4-edge row kernel (proven structure) + R13 delta: slot list
// pre-loaded into registers (lane i holds slot i, coalesced LDG.64) and col
// indices fetched via shfl (26 cyc) instead of per-iteration broadcast L2
// loads (~250 cyc). deg>32 tail (expected ~1.5 rows total) falls back to
// direct loads. k-gather / reduction / store paths unchanged.
// ---------------------------------------------------------------------------
__global__ __launch_bounds__(256) void row_kernel(float* __restrict__ out)
{
    __shared__ float exbuf[8][SLOTS][2];         // 8 KB

    const int w    = threadIdx.x >> 5;
    const int lane = threadIdx.x & 31;
    const int row  = blockIdx.x * 8 + w;
    if (row >= NN) return;

    const int sub = lane >> 4;                   // which edge of the pair
    const int h   = (lane >> 3) & 1;             // head
    const int c   = lane & 7;                    // chunk of 8 floats

    const float4* qp = reinterpret_cast<const float4*>(
        g_qk + (size_t)row * CC + h * 128 + c * 8);
    const float4 qa = qp[0];
    const float4 qb = qp[1];

    int deg = g_cnt[row];
    if (deg > SLOTS) deg = SLOTS;
    const int2* sl = g_slots + (size_t)row * SLOTS;

    // R13: lane i caches slot i (coalesced, guarded, aligned int2)
    int2 myslot = make_int2(0, 0);
    if (lane < deg) myslot = sl[lane];

    float denom = 0.0f;                          // valid on lanes 0, 8, 16, 24

    for (int i0 = 0; i0 < deg; i0 += 4) {
        const int iA = i0 + sub;
        const int iB = i0 + 2 + sub;
        const bool vA = iA < deg;
        const bool vB = iB < deg;

        // col via register shfl (all lanes participate; fallback for i>=32)
        int colA = __shfl_sync(0xffffffffu, myslot.x, iA & 31);
        int colB = __shfl_sync(0xffffffffu, myslot.x, iB & 31);
        if (iA >= 32 && vA) colA = sl[iA].x;
        if (iB >= 32 && vB) colB = sl[iB].x;
        if (!vA) colA = 0;
        if (!vB) colB = 0;

        const float4* kA = reinterpret_cast<const float4*>(
            g_qk + (size_t)colA * CC + h * 128 + 64 + c * 8);
        const float4* kB = reinterpret_cast<const float4*>(
            g_qk + (size_t)colB * CC + h * 128 + 64 + c * 8);
        float4 ka0 = kA[0], ka1 = kA[1];
        float4 kb0 = kB[0], kb1 = kB[1];

        float sA = qa.x * ka0.x + qa.y * ka0.y + qa.z * ka0.z + qa.w * ka0.w
                 + qb.x * ka1.x + qb.y * ka1.y + qb.z * ka1.z + qb.w * ka1.w;
        float sB = qa.x * kb0.x + qa.y * kb0.y + qa.z * kb0.z + qa.w * kb0.w
                 + qb.x * kb1.x + qb.y * kb1.y + qb.z * kb1.z + qb.w * kb1.w;

        sA += __shfl_xor_sync(0xffffffffu, sA, 1);
        sB += __shfl_xor_sync(0xffffffffu, sB, 1);
        sA += __shfl_xor_sync(0xffffffffu, sA, 2);
        sB += __shfl_xor_sync(0xffffffffu, sB, 2);
        sA += __shfl_xor_sync(0xffffffffu, sA, 4);
        sB += __shfl_xor_sync(0xffffffffu, sB, 4);

        if (c == 0) {
            if (vA) {
                float ex = __expf(sA);           // |s| <~ 15: no max-shift needed
                exbuf[w][iA][h] = ex;
                denom += ex;
            }
            if (vB) {
                float ex = __expf(sB);
                exbuf[w][iB][h] = ex;
                denom += ex;
            }
        }
    }

    float d0 = __shfl_sync(0xffffffffu, denom, 0)
             + __shfl_sync(0xffffffffu, denom, 16);   // head 0
    float d1 = __shfl_sync(0xffffffffu, denom, 8)
             + __shfl_sync(0xffffffffu, denom, 24);   // head 1
    float c0 = 0.5f / d0;
    float c1 = 0.5f / d1;
    __syncwarp();

    for (int i = lane; i < deg; i += 32) {
        int2 sc = (i < 32) ? myslot : sl[i];     // i==lane on first pass
        out[sc.y] = exbuf[w][i][0] * c0 + exbuf[w][i][1] * c1;
    }
}

// ---------------------------------------------------------------------------
extern "C" void kernel_launch(void* const* d_in, const int* in_sizes, int n_in,
                              void* d_out, int out_size)
{
    const float* x   = (const float*)d_in[0];    // [50000, 64]
    const float* W   = (const float*)d_in[1];    // [64, 256]
    const float* b   = (const float*)d_in[2];    // [256]
    const int*   ei  = (const int*)  d_in[3];    // [2, 800000]
    float*       out = (float*)d_out;            // [800000]

    (void)in_sizes; (void)n_in; (void)out_size;

    // zero the row cursors (graph-capturable async memset)
    void* cnt_ptr = nullptr;
    cudaGetSymbolAddress(&cnt_ptr, g_cnt);
    cudaMemsetAsync(cnt_ptr, 0, NN * sizeof(int));

    gemm_kernel<<<(NN + NODES_PER_BLOCK - 1) / NODES_PER_BLOCK, 128>>>(x, W, b);
    scatter_kernel<<<(EE + 255) / 256, 256>>>(ei);
    row_kernel<<<(NN + 7) / 8, 256>>>(out);
}